// round 13
// baseline (speedup 1.0000x reference)
#include <cuda_runtime.h>
#include <cuda_fp16.h>
#include <math.h>
#include <stdint.h>

// ---------------- problem constants ----------------
#define Bsz 16
#define Nn  1024
#define HIDc 64
#define T1  10
#define OC  384
#define Ee  16384
#define BT1 (Bsz*T1)    // 160
#define STAT_CNT 49152.0f

// smem strides (u32 units)
#define A_ST 36          // 64 halves = 32 u32 + 4 pad -> a-frag 4r+c conflict-free
#define B_ST 136         // 128 u32 payload + 8 pad -> b-frag LDS.64 conflict-free
#define B_W16 (12 * B_ST)

// ---------------- helpers ----------------
__device__ __forceinline__ uint32_t pack_h2(float x, float y) {
    __half2 h = __floats2half2_rn(x, y);
    return *reinterpret_cast<uint32_t*>(&h);
}
__device__ __forceinline__ float2 h2f2(uint32_t u) {
    __half2 h = *reinterpret_cast<__half2*>(&u);
    return __half22float2(h);
}
__device__ __forceinline__ void mma_f16(float c[4], const uint32_t a[4],
                                        uint32_t b0, uint32_t b1) {
    asm volatile(
        "mma.sync.aligned.m16n8k16.row.col.f32.f16.f16.f32 "
        "{%0,%1,%2,%3},{%4,%5,%6,%7},{%8,%9},{%0,%1,%2,%3};"
        : "+f"(c[0]), "+f"(c[1]), "+f"(c[2]), "+f"(c[3])
        : "r"(a[0]), "r"(a[1]), "r"(a[2]), "r"(a[3]), "r"(b0), "r"(b1));
}

// ---------------- device scratch ----------------
__device__ __half g_T0h [Nn*BT1*HIDc];
__device__ __half g_Tx1h[Nn*BT1*HIDc];
__device__ __half g_Tx2h[Nn*BT1*HIDc];
__device__ __half g_Tgh [Nn*BT1*HIDc];
__device__ float  g_last[Bsz*Nn*OC];
__device__ uint32_t g_wth[12*3*4*OC*2];  // [kc][s][c][o][p] half2-as-u32
__device__ uint32_t g_cwh[3*4*4*64*2];   // [s][kc][c][n][p]
__device__ int   g_cntv[Nn];
__device__ int   g_indptr[Nn];
__device__ int   g_csr_row[Ee];
__device__ float g_csr_nrm[Ee];
__device__ float g_sum[Nn];
__device__ float g_sumsq[Nn];

// ---------------- CSR build: one block, smem atomics ----------------
__global__ __launch_bounds__(1024) void k_csr(const int* __restrict__ ei,
                                              const float* __restrict__ ew) {
    __shared__ float sdeg[Nn];
    __shared__ int   scnt[Nn];
    __shared__ float sdinv[Nn];
    __shared__ int   sptr[Nn];
    __shared__ int   scounter[Nn];
    int t = threadIdx.x;
    sdeg[t] = 0.f; scnt[t] = 0; scounter[t] = 0;
    g_sum[t] = 0.f; g_sumsq[t] = 0.f;
    __syncthreads();
#pragma unroll
    for (int q = 0; q < 16; q++) {
        int e = t + q * 1024;
        int r = ei[e], c = ei[Ee + e];
        float w = ew[e];
        if (r != c) atomicAdd(&sdeg[r], w);
        atomicAdd(&scnt[c], 1);
    }
    __syncthreads();
    float d = sdeg[t];
    sdinv[t] = (d > 0.f) ? rsqrtf(d) : 0.f;
    int cval = scnt[t];
    sptr[t] = cval;
    __syncthreads();
    for (int off = 1; off < Nn; off <<= 1) {
        int v = (t >= off) ? sptr[t - off] : 0;
        __syncthreads();
        sptr[t] += v;
        __syncthreads();
    }
    int excl = sptr[t] - cval;
    __syncthreads();
    sptr[t] = excl;
    g_cntv[t] = cval;
    g_indptr[t] = excl;
    __syncthreads();
#pragma unroll
    for (int q = 0; q < 16; q++) {
        int e = t + q * 1024;
        int r = ei[e], c = ei[Ee + e];
        float w = ew[e];
        float nm = (r == c) ? 0.f : -(sdinv[r] * w * sdinv[c]);
        int pos = sptr[c] + atomicAdd(&scounter[c], 1);
        g_csr_row[pos] = r;
        g_csr_nrm[pos] = nm;
    }
}

// ---------------- temporal conv 1 (writes fp16) ----------------
__global__ __launch_bounds__(64) void k_conv1(
    const float* __restrict__ X,
    const float* __restrict__ w1, const float* __restrict__ b1,
    const float* __restrict__ w2, const float* __restrict__ b2,
    const float* __restrict__ w3, const float* __restrict__ b3)
{
    int bid = blockIdx.x;
    int n = bid >> 4, b = bid & 15;
    int h = threadIdx.x;
    __shared__ float sx[2][12];
    if (h < 24) {
        int c = h / 12, t = h % 12;
        sx[c][t] = X[((b * Nn + n) * 2 + c) * 12 + t];
    }
    float w1r[6], w2r[6], w3r[6];
#pragma unroll
    for (int j = 0; j < 6; j++) {
        w1r[j] = w1[h * 6 + j];
        w2r[j] = w2[h * 6 + j];
        w3r[j] = w3[h * 6 + j];
    }
    float bb1 = b1[h], bb2 = b2[h], bb3 = b3[h];
    __syncthreads();
#pragma unroll
    for (int tp = 0; tp < T1; tp++) {
        float P = bb1, Q = bb2, R = bb3;
#pragma unroll
        for (int c = 0; c < 2; c++)
#pragma unroll
            for (int k = 0; k < 3; k++) {
                float v = sx[c][tp + k];
                P += v * w1r[c * 3 + k];
                Q += v * w2r[c * 3 + k];
                R += v * w3r[c * 3 + k];
            }
        float sg = 1.f / (1.f + expf(-Q));
        float val = P * sg + R;
        val = val > 0.f ? val : 0.f;
        g_T0h[(n * BT1 + b * T1 + tp) * HIDc + h] = __float2half_rn(val);
    }
}

// ---------------- weight prep (merged): conv2 + cheb fp16 fragment layouts ----------------
__global__ void k_wprep(const float* __restrict__ w1,
                        const float* __restrict__ w2,
                        const float* __restrict__ w3,
                        const float* __restrict__ chebW)
{
    int idx = blockIdx.x * blockDim.x + threadIdx.x;
    if (idx < 110592) {
        int p = idx & 1;
        int rem = idx >> 1;
        int o = rem % 384;
        int rem2 = rem / 384;
        int c = rem2 & 3;
        int rem3 = rem2 >> 2;
        int s = rem3 % 3;
        int kc = rem3 / 3;
        const float* w = (s == 0) ? w1 : (s == 1) ? w2 : w3;
        int dt = kc >> 2;
        int h0 = (kc & 3) * 16 + 2 * c + 8 * p;
        float lo = w[(o * HIDc + h0) * 3 + dt];
        float hi = w[(o * HIDc + h0 + 1) * 3 + dt];
        g_wth[((kc * 3 + s) * 4 + c) * 768 + o * 2 + p] = pack_h2(lo, hi);
    } else if (idx < 110592 + 6144) {
        int j = idx - 110592;
        int p = j & 1;
        int n = (j >> 1) & 63;
        int c = (j >> 7) & 3;
        int kc = (j >> 9) & 3;
        int s = j >> 11;
        int k0 = kc * 16 + 2 * c + 8 * p;
        float lo = chebW[s * 4096 + k0 * HIDc + n];
        float hi = chebW[s * 4096 + (k0 + 1) * HIDc + n];
        g_cwh[j] = pack_h2(lo, hi);
    }
}

// ---------------- graph propagation: fp16 gather, fp32 accumulate ----------------
// grid (Nn, 2): node x bt-half. 128 threads: hq = tid&7 (full 128B row), g = tid>>3 (16 groups x 5 bt).
__global__ __launch_bounds__(128) void k_prop(int mode) {
    const __half* __restrict__ z = (mode == 0) ? g_T0h : g_Tx1h;
    __half* __restrict__ out = (mode == 0) ? g_Tx1h : g_Tx2h;
    int j = blockIdx.x;
    int bt0 = blockIdx.y * 80;
    int tid = threadIdx.x;
    int hq = tid & 7;
    int g = tid >> 3;                     // 0..15
    float2 acc[5][4];
#pragma unroll
    for (int i = 0; i < 5; i++)
#pragma unroll
        for (int k = 0; k < 4; k++) acc[i][k] = make_float2(0.f, 0.f);

    int start = g_indptr[j], cnt = g_cntv[j];
    __shared__ int sr[64];
    __shared__ float sn[64];
    for (int eb = 0; eb < cnt; eb += 64) {
        int m = cnt - eb; if (m > 64) m = 64;
        if (tid < m) { sr[tid] = g_csr_row[start + eb + tid]; sn[tid] = g_csr_nrm[start + eb + tid]; }
        __syncthreads();
        int e = 0;
        for (; e + 2 <= m; e += 2) {
            int r0 = sr[e], r1 = sr[e + 1];
            float nm0 = sn[e], nm1 = sn[e + 1];
            const uint4* zp0 = (const uint4*)z + (size_t)(r0 * BT1 + bt0 + g * 5) * 8 + hq;
            const uint4* zp1 = (const uint4*)z + (size_t)(r1 * BT1 + bt0 + g * 5) * 8 + hq;
#pragma unroll
            for (int i = 0; i < 5; i++) {
                uint4 va = zp0[(size_t)i * 8];
                uint4 vb = zp1[(size_t)i * 8];
                float2 f0 = h2f2(va.x), f1 = h2f2(va.y), f2 = h2f2(va.z), f3 = h2f2(va.w);
                acc[i][0].x += nm0 * f0.x; acc[i][0].y += nm0 * f0.y;
                acc[i][1].x += nm0 * f1.x; acc[i][1].y += nm0 * f1.y;
                acc[i][2].x += nm0 * f2.x; acc[i][2].y += nm0 * f2.y;
                acc[i][3].x += nm0 * f3.x; acc[i][3].y += nm0 * f3.y;
                float2 g0 = h2f2(vb.x), g1 = h2f2(vb.y), g2 = h2f2(vb.z), g3 = h2f2(vb.w);
                acc[i][0].x += nm1 * g0.x; acc[i][0].y += nm1 * g0.y;
                acc[i][1].x += nm1 * g1.x; acc[i][1].y += nm1 * g1.y;
                acc[i][2].x += nm1 * g2.x; acc[i][2].y += nm1 * g2.y;
                acc[i][3].x += nm1 * g3.x; acc[i][3].y += nm1 * g3.y;
            }
        }
        if (e < m) {
            int r0 = sr[e];
            float nm0 = sn[e];
            const uint4* zp0 = (const uint4*)z + (size_t)(r0 * BT1 + bt0 + g * 5) * 8 + hq;
#pragma unroll
            for (int i = 0; i < 5; i++) {
                uint4 va = zp0[(size_t)i * 8];
                float2 f0 = h2f2(va.x), f1 = h2f2(va.y), f2 = h2f2(va.z), f3 = h2f2(va.w);
                acc[i][0].x += nm0 * f0.x; acc[i][0].y += nm0 * f0.y;
                acc[i][1].x += nm0 * f1.x; acc[i][1].y += nm0 * f1.y;
                acc[i][2].x += nm0 * f2.x; acc[i][2].y += nm0 * f2.y;
                acc[i][3].x += nm0 * f3.x; acc[i][3].y += nm0 * f3.y;
            }
        }
        __syncthreads();
    }
    uint4* op = (uint4*)out + (size_t)(j * BT1 + bt0 + g * 5) * 8 + hq;
    if (mode == 0) {
#pragma unroll
        for (int i = 0; i < 5; i++) {
            uint4 o4;
            o4.x = pack_h2(acc[i][0].x, acc[i][0].y);
            o4.y = pack_h2(acc[i][1].x, acc[i][1].y);
            o4.z = pack_h2(acc[i][2].x, acc[i][2].y);
            o4.w = pack_h2(acc[i][3].x, acc[i][3].y);
            op[(size_t)i * 8] = o4;
        }
    } else {
        const uint4* sp = (const uint4*)g_T0h + (size_t)(j * BT1 + bt0 + g * 5) * 8 + hq;
#pragma unroll
        for (int i = 0; i < 5; i++) {
            uint4 s0 = sp[(size_t)i * 8];
            float2 t0 = h2f2(s0.x), t1 = h2f2(s0.y), t2 = h2f2(s0.z), t3 = h2f2(s0.w);
            uint4 o4;
            o4.x = pack_h2(2.f * acc[i][0].x - t0.x, 2.f * acc[i][0].y - t0.y);
            o4.y = pack_h2(2.f * acc[i][1].x - t1.x, 2.f * acc[i][1].y - t1.y);
            o4.z = pack_h2(2.f * acc[i][2].x - t2.x, 2.f * acc[i][2].y - t2.y);
            o4.w = pack_h2(2.f * acc[i][3].x - t3.x, 2.f * acc[i][3].y - t3.y);
            op[(size_t)i * 8] = o4;
        }
    }
}

// ---------------- cheb combine: fp16 mma m16n8k16 ----------------
__global__ __launch_bounds__(256) void k_chebmm(const float* __restrict__ chebB)
{
    __shared__ uint32_t sA[64 * A_ST];
    __shared__ uint32_t sB[16 * B_ST];
    int m0 = blockIdx.x * 64;
    int tid = threadIdx.x;
    int lane = tid & 31, w = tid >> 5;
    int mw = w & 3, nh = w >> 2;
    int r = lane >> 2, c = lane & 3;

    float acc[4][4];
#pragma unroll
    for (int nt = 0; nt < 4; nt++)
#pragma unroll
        for (int i = 0; i < 4; i++) acc[nt][i] = 0.f;

    const __half* srcs[3] = { g_T0h, g_Tx1h, g_Tx2h };
    for (int s = 0; s < 3; s++) {
        const uint4* gA = (const uint4*)(srcs[s] + (size_t)m0 * HIDc);
#pragma unroll
        for (int q = 0; q < 2; q++) {
            int i4 = tid + q * 256;
            int row = i4 >> 3, h8 = i4 & 7;
            *(uint4*)&sA[row * A_ST + h8 * 4] = gA[i4];
        }
        const uint2* gB = (const uint2*)g_cwh + s * 1024;
#pragma unroll
        for (int q = 0; q < 4; q++) {
            int i2 = tid + q * 256;
            int rr = i2 >> 6, nn = i2 & 63;
            *(uint2*)&sB[rr * B_ST + nn * 2] = gB[i2];
        }
        __syncthreads();
#pragma unroll
        for (int kc = 0; kc < 4; kc++) {
            uint32_t a[4];
            int abase = (mw * 16 + r) * A_ST + kc * 8 + c;
            a[0] = sA[abase];
            a[1] = sA[abase + 8 * A_ST];
            a[2] = sA[abase + 4];
            a[3] = sA[abase + 8 * A_ST + 4];
#pragma unroll
            for (int nt = 0; nt < 4; nt++) {
                uint2 bv = *(const uint2*)&sB[(kc * 4 + c) * B_ST + (nh * 32 + nt * 8 + r) * 2];
                mma_f16(acc[nt], a, bv.x, bv.y);
            }
        }
        __syncthreads();
    }
#pragma unroll
    for (int nt = 0; nt < 4; nt++) {
        int n0 = nh * 32 + nt * 8 + c * 2;
        float bb0 = chebB[n0], bb1 = chebB[n0 + 1];
        float v0 = acc[nt][0] + bb0; v0 = v0 > 0.f ? v0 : 0.f;
        float v1 = acc[nt][1] + bb1; v1 = v1 > 0.f ? v1 : 0.f;
        float v2 = acc[nt][2] + bb0; v2 = v2 > 0.f ? v2 : 0.f;
        float v3 = acc[nt][3] + bb1; v3 = v3 > 0.f ? v3 : 0.f;
        *(uint32_t*)&g_Tgh[(size_t)(m0 + mw * 16 + r) * HIDc + n0] = pack_h2(v0, v1);
        *(uint32_t*)&g_Tgh[(size_t)(m0 + mw * 16 + r + 8) * HIDc + n0] = pack_h2(v2, v3);
    }
}

// ---------------- temporal conv 2: fp16 mma, A resident, b-frag reuse x2 ----------------
__global__ __launch_bounds__(256) void k_conv2(
    const float* __restrict__ b1, const float* __restrict__ b2, const float* __restrict__ b3)
{
    __shared__ uint32_t sA[BT1 * A_ST];
    __shared__ uint32_t sB[2 * B_W16];
    int n = blockIdx.y;
    int o0 = blockIdx.x * 64;
    int tid = threadIdx.x;
    int lane = tid & 31, w = tid >> 5;
    int mp = w & 3, nh = w >> 2;
    int r = lane >> 2, c = lane & 3;

    const uint4* gT = (const uint4*)(g_Tgh + (size_t)n * (BT1 * HIDc));
#pragma unroll
    for (int q = 0; q < 5; q++) {
        int i4 = tid + q * 256;
        int bt = i4 >> 3, h8 = i4 & 7;
        *(uint4*)&sA[bt * A_ST + h8 * 4] = gT[i4];
    }
    const uint2* gW2 = (const uint2*)g_wth;
#pragma unroll
    for (int q = 0; q < 3; q++) {
        int i2 = tid + q * 256;
        int rr = i2 >> 6, nn = i2 & 63;
        *(uint2*)&sB[rr * B_ST + nn * 2] = gW2[rr * 384 + o0 + nn];
    }
    __syncthreads();

    float acc[3][2][4][4];
#pragma unroll
    for (int s = 0; s < 3; s++)
#pragma unroll
        for (int mt = 0; mt < 2; mt++)
#pragma unroll
            for (int nt = 0; nt < 4; nt++)
#pragma unroll
                for (int i = 0; i < 4; i++) acc[s][mt][nt][i] = 0.f;

    for (int kc = 0; kc < 12; kc++) {
        int cur = (kc & 1) ? B_W16 : 0;
        if (kc < 11) {
            int nxt = B_W16 - cur;
            int gbase = (kc + 1) * 12 * 384;
#pragma unroll
            for (int q = 0; q < 3; q++) {
                int i2 = tid + q * 256;
                int rr = i2 >> 6, nn = i2 & 63;
                *(uint2*)&sB[nxt + rr * B_ST + nn * 2] = gW2[gbase + rr * 384 + o0 + nn];
            }
        }
        int dt = kc >> 2;
        int hb2 = (kc & 3) * 8;
        uint32_t a[2][4];
#pragma unroll
        for (int mt = 0; mt < 2; mt++) {
            int base0 = (20 * (2 * mp + mt) + r + dt) * A_ST + hb2 + c;
            a[mt][0] = sA[base0];
            a[mt][1] = sA[base0 + 10 * A_ST];
            a[mt][2] = sA[base0 + 4];
            a[mt][3] = sA[base0 + 10 * A_ST + 4];
        }
#pragma unroll
        for (int s = 0; s < 3; s++)
#pragma unroll
            for (int nt = 0; nt < 4; nt++) {
                uint2 bv = *(const uint2*)&sB[cur + (s * 4 + c) * B_ST + ((nh * 4 + nt) * 8 + r) * 2];
                mma_f16(acc[s][0][nt], a[0], bv.x, bv.y);
                mma_f16(acc[s][1][nt], a[1], bv.x, bv.y);
            }
        __syncthreads();
    }

    int col2 = c * 2;
    float lsum = 0.f, lss = 0.f;
#pragma unroll
    for (int nt = 0; nt < 4; nt++) {
#pragma unroll
        for (int cc = 0; cc < 2; cc++) {
            int o = o0 + (nh * 4 + nt) * 8 + col2 + cc;
            float bias1 = b1[o], bias2 = b2[o], bias3 = b3[o];
#pragma unroll
            for (int mt = 0; mt < 2; mt++) {
#pragma unroll
                for (int rh = 0; rh < 2; rh++) {
                    float P = acc[0][mt][nt][rh * 2 + cc] + bias1;
                    float Q = acc[1][mt][nt][rh * 2 + cc] + bias2;
                    float R = acc[2][mt][nt][rh * 2 + cc] + bias3;
                    float sg = 1.f / (1.f + expf(-Q));
                    float v = P * sg + R;
                    v = v > 0.f ? v : 0.f;
                    lsum += v;
                    lss += v * v;
                    if (r == 7) {
                        int b = 2 * (2 * mp + mt) + rh;
                        g_last[(size_t)(b * Nn + n) * OC + o] = v;
                    }
                }
            }
        }
    }

#pragma unroll
    for (int off = 16; off > 0; off >>= 1) {
        lsum += __shfl_down_sync(0xffffffffu, lsum, off);
        lss  += __shfl_down_sync(0xffffffffu, lss,  off);
    }
    __shared__ float wsum[8], wss[8];
    if (lane == 0) { wsum[w] = lsum; wss[w] = lss; }
    __syncthreads();
    if (tid == 0) {
        float ts = 0.f, tq = 0.f;
#pragma unroll
        for (int i = 0; i < 8; i++) { ts += wsum[i]; tq += wss[i]; }
        atomicAdd(&g_sum[n], ts);
        atomicAdd(&g_sumsq[n], tq);
    }
}

// ---------------- final: BN + coalesced transpose via smem tile ----------------
__global__ __launch_bounds__(256) void k_final(
    const float* __restrict__ gamma, const float* __restrict__ beta,
    float* __restrict__ out)
{
    __shared__ float s[32][129];
    __shared__ float smean[32], sinv[32], sga[32], sbe[32];
    int n0 = blockIdx.x * 32;
    int c0 = blockIdx.y * 128;
    int b  = blockIdx.z;
    int tid = threadIdx.x;
    if (tid < 32) {
        int n = n0 + tid;
        float mean = g_sum[n] / STAT_CNT;
        float var = g_sumsq[n] / STAT_CNT - mean * mean;
        smean[tid] = mean;
        sinv[tid] = rsqrtf(var + 1e-5f);
        sga[tid] = gamma[n];
        sbe[tid] = beta[n];
    }
    int cl = tid & 63;
    int nl = tid >> 6;
#pragma unroll
    for (int i = 0; i < 8; i++) {
        int nn = nl + i * 4;
        float2 v = *(const float2*)&g_last[((size_t)(b * Nn) + n0 + nn) * OC + c0 + cl * 2];
        s[nn][cl * 2] = v.x;
        s[nn][cl * 2 + 1] = v.y;
    }
    __syncthreads();
    int nw = tid & 31, cw = tid >> 5;
    float mean = smean[nw], inv = sinv[nw];
    float ga = sga[nw], be = sbe[nw];
#pragma unroll
    for (int j = 0; j < 16; j++) {
        int c = cw + j * 8;
        out[(size_t)(c0 + c) * (Bsz * Nn) + b * Nn + n0 + nw] =
            (s[nw][c] - mean) * inv * ga + be;
    }
}

// ---------------- launch ----------------
extern "C" void kernel_launch(void* const* d_in, const int* in_sizes, int n_in,
                              void* d_out, int out_size)
{
    const float* X        = (const float*)d_in[0];
    const int*   ei       = (const int*)  d_in[1];
    const float* ew       = (const float*)d_in[2];
    const float* tc1_w1   = (const float*)d_in[3];
    const float* tc1_b1   = (const float*)d_in[4];
    const float* tc1_w2   = (const float*)d_in[5];
    const float* tc1_b2   = (const float*)d_in[6];
    const float* tc1_w3   = (const float*)d_in[7];
    const float* tc1_b3   = (const float*)d_in[8];
    const float* cheb_W   = (const float*)d_in[9];
    const float* cheb_b   = (const float*)d_in[10];
    const float* tc2_w1   = (const float*)d_in[11];
    const float* tc2_b1   = (const float*)d_in[12];
    const float* tc2_w2   = (const float*)d_in[13];
    const float* tc2_b2   = (const float*)d_in[14];
    const float* tc2_w3   = (const float*)d_in[15];
    const float* tc2_b3   = (const float*)d_in[16];
    const float* bn_gamma = (const float*)d_in[17];
    const float* bn_beta  = (const float*)d_in[18];
    float* out = (float*)d_out;

    k_csr<<<1, 1024>>>(ei, ew);
    k_conv1<<<Bsz * Nn, 64>>>(X, tc1_w1, tc1_b1, tc1_w2, tc1_b2, tc1_w3, tc1_b3);
    k_wprep<<<(110592 + 6144 + 255) / 256, 256>>>(tc2_w1, tc2_w2, tc2_w3, cheb_W);
    k_prop<<<dim3(Nn, 2), 128>>>(0);
    k_prop<<<dim3(Nn, 2), 128>>>(1);
    k_chebmm<<<(Nn * BT1) / 64, 256>>>(cheb_b);
    k_conv2<<<dim3(6, Nn), 256>>>(tc2_b1, tc2_b2, tc2_b3);
    k_final<<<dim3(32, 3, 16), 256>>>(bn_gamma, bn_beta, out);
}

// round 14
// speedup vs baseline: 1.6734x; 1.6734x over previous
#include <cuda_runtime.h>
#include <cuda_fp16.h>
#include <math.h>
#include <stdint.h>

// ---------------- problem constants ----------------
#define Bsz 16
#define Nn  1024
#define HIDc 64
#define T1  10
#define OC  384
#define Ee  16384
#define BT1 (Bsz*T1)    // 160
#define STAT_CNT 49152.0f

// smem strides (u32 units)
#define A_ST 36          // 64 halves = 32 u32 + 4 pad -> a-frag 4r+c conflict-free
#define B_ST 136         // 128 u32 payload + 8 pad -> b-frag LDS.64 conflict-free
#define B_W16 (12 * B_ST)

// ---------------- helpers ----------------
__device__ __forceinline__ uint32_t pack_h2(float x, float y) {
    __half2 h = __floats2half2_rn(x, y);
    return *reinterpret_cast<uint32_t*>(&h);
}
__device__ __forceinline__ float2 h2f2(uint32_t u) {
    __half2 h = *reinterpret_cast<__half2*>(&u);
    return __half22float2(h);
}
__device__ __forceinline__ void mma_f16(float c[4], const uint32_t a[4],
                                        uint32_t b0, uint32_t b1) {
    asm volatile(
        "mma.sync.aligned.m16n8k16.row.col.f32.f16.f16.f32 "
        "{%0,%1,%2,%3},{%4,%5,%6,%7},{%8,%9},{%0,%1,%2,%3};"
        : "+f"(c[0]), "+f"(c[1]), "+f"(c[2]), "+f"(c[3])
        : "r"(a[0]), "r"(a[1]), "r"(a[2]), "r"(a[3]), "r"(b0), "r"(b1));
}

// ---------------- device scratch ----------------
__device__ __half g_T0h [Nn*BT1*HIDc];
__device__ __half g_Tx1h[Nn*BT1*HIDc];
__device__ __half g_Tx2h[Nn*BT1*HIDc];
__device__ __half g_Tgh [Nn*BT1*HIDc];
__device__ float  g_last[Bsz*Nn*OC];
__device__ uint32_t g_wth[12*3*4*OC*2];  // [kc][s][c][o][p] half2-as-u32
__device__ uint32_t g_cwh[3*4*4*64*2];   // [s][kc][c][n][p]
__device__ int   g_cntv[Nn];
__device__ int   g_indptr[Nn];
__device__ int   g_csr_row[Ee];
__device__ float g_csr_nrm[Ee];
__device__ float g_sum[Nn];
__device__ float g_sumsq[Nn];

// ---------------- CSR build: one block, smem atomics ----------------
__global__ __launch_bounds__(1024) void k_csr(const int* __restrict__ ei,
                                              const float* __restrict__ ew) {
    __shared__ float sdeg[Nn];
    __shared__ int   scnt[Nn];
    __shared__ float sdinv[Nn];
    __shared__ int   sptr[Nn];
    __shared__ int   scounter[Nn];
    int t = threadIdx.x;
    sdeg[t] = 0.f; scnt[t] = 0; scounter[t] = 0;
    g_sum[t] = 0.f; g_sumsq[t] = 0.f;
    __syncthreads();
#pragma unroll
    for (int q = 0; q < 16; q++) {
        int e = t + q * 1024;
        int r = ei[e], c = ei[Ee + e];
        float w = ew[e];
        if (r != c) atomicAdd(&sdeg[r], w);
        atomicAdd(&scnt[c], 1);
    }
    __syncthreads();
    float d = sdeg[t];
    sdinv[t] = (d > 0.f) ? rsqrtf(d) : 0.f;
    int cval = scnt[t];
    sptr[t] = cval;
    __syncthreads();
    for (int off = 1; off < Nn; off <<= 1) {
        int v = (t >= off) ? sptr[t - off] : 0;
        __syncthreads();
        sptr[t] += v;
        __syncthreads();
    }
    int excl = sptr[t] - cval;
    __syncthreads();
    sptr[t] = excl;
    g_cntv[t] = cval;
    g_indptr[t] = excl;
    __syncthreads();
#pragma unroll
    for (int q = 0; q < 16; q++) {
        int e = t + q * 1024;
        int r = ei[e], c = ei[Ee + e];
        float w = ew[e];
        float nm = (r == c) ? 0.f : -(sdinv[r] * w * sdinv[c]);
        int pos = sptr[c] + atomicAdd(&scounter[c], 1);
        g_csr_row[pos] = r;
        g_csr_nrm[pos] = nm;
    }
}

// ---------------- temporal conv 1 (writes fp16) ----------------
__global__ __launch_bounds__(64) void k_conv1(
    const float* __restrict__ X,
    const float* __restrict__ w1, const float* __restrict__ b1,
    const float* __restrict__ w2, const float* __restrict__ b2,
    const float* __restrict__ w3, const float* __restrict__ b3)
{
    int bid = blockIdx.x;
    int n = bid >> 4, b = bid & 15;
    int h = threadIdx.x;
    __shared__ float sx[2][12];
    if (h < 24) {
        int c = h / 12, t = h % 12;
        sx[c][t] = X[((b * Nn + n) * 2 + c) * 12 + t];
    }
    float w1r[6], w2r[6], w3r[6];
#pragma unroll
    for (int j = 0; j < 6; j++) {
        w1r[j] = w1[h * 6 + j];
        w2r[j] = w2[h * 6 + j];
        w3r[j] = w3[h * 6 + j];
    }
    float bb1 = b1[h], bb2 = b2[h], bb3 = b3[h];
    __syncthreads();
#pragma unroll
    for (int tp = 0; tp < T1; tp++) {
        float P = bb1, Q = bb2, R = bb3;
#pragma unroll
        for (int c = 0; c < 2; c++)
#pragma unroll
            for (int k = 0; k < 3; k++) {
                float v = sx[c][tp + k];
                P += v * w1r[c * 3 + k];
                Q += v * w2r[c * 3 + k];
                R += v * w3r[c * 3 + k];
            }
        float sg = 1.f / (1.f + expf(-Q));
        float val = P * sg + R;
        val = val > 0.f ? val : 0.f;
        g_T0h[(n * BT1 + b * T1 + tp) * HIDc + h] = __float2half_rn(val);
    }
}

// ---------------- weight prep (merged): conv2 + cheb fp16 fragment layouts ----------------
__global__ void k_wprep(const float* __restrict__ w1,
                        const float* __restrict__ w2,
                        const float* __restrict__ w3,
                        const float* __restrict__ chebW)
{
    int idx = blockIdx.x * blockDim.x + threadIdx.x;
    if (idx < 110592) {
        int p = idx & 1;
        int rem = idx >> 1;
        int o = rem % 384;
        int rem2 = rem / 384;
        int c = rem2 & 3;
        int rem3 = rem2 >> 2;
        int s = rem3 % 3;
        int kc = rem3 / 3;
        const float* w = (s == 0) ? w1 : (s == 1) ? w2 : w3;
        int dt = kc >> 2;
        int h0 = (kc & 3) * 16 + 2 * c + 8 * p;
        float lo = w[(o * HIDc + h0) * 3 + dt];
        float hi = w[(o * HIDc + h0 + 1) * 3 + dt];
        g_wth[((kc * 3 + s) * 4 + c) * 768 + o * 2 + p] = pack_h2(lo, hi);
    } else if (idx < 110592 + 6144) {
        int j = idx - 110592;
        int p = j & 1;
        int n = (j >> 1) & 63;
        int c = (j >> 7) & 3;
        int kc = (j >> 9) & 3;
        int s = j >> 11;
        int k0 = kc * 16 + 2 * c + 8 * p;
        float lo = chebW[s * 4096 + k0 * HIDc + n];
        float hi = chebW[s * 4096 + (k0 + 1) * HIDc + n];
        g_cwh[j] = pack_h2(lo, hi);
    }
}

// ---------------- graph propagation: fp16 gather, fp32 accumulate, edge-unroll x2 ----------------
// grid Nn, 256 threads: hq = tid&7, g = tid>>3 (32 groups x 5 bt). (R11 champion shape)
__global__ __launch_bounds__(256) void k_prop(int mode) {
    const __half* __restrict__ z = (mode == 0) ? g_T0h : g_Tx1h;
    __half* __restrict__ out = (mode == 0) ? g_Tx1h : g_Tx2h;
    int j = blockIdx.x;
    int tid = threadIdx.x;
    int hq = tid & 7;
    int g = tid >> 3;
    float2 acc[5][4];
#pragma unroll
    for (int i = 0; i < 5; i++)
#pragma unroll
        for (int k = 0; k < 4; k++) acc[i][k] = make_float2(0.f, 0.f);

    int start = g_indptr[j], cnt = g_cntv[j];
    __shared__ int sr[64];
    __shared__ float sn[64];
    for (int eb = 0; eb < cnt; eb += 64) {
        int m = cnt - eb; if (m > 64) m = 64;
        if (tid < m) { sr[tid] = g_csr_row[start + eb + tid]; sn[tid] = g_csr_nrm[start + eb + tid]; }
        __syncthreads();
        int e = 0;
        for (; e + 2 <= m; e += 2) {
            int r0 = sr[e], r1 = sr[e + 1];
            float nm0 = sn[e], nm1 = sn[e + 1];
            const uint4* zp0 = (const uint4*)z + (size_t)(r0 * BT1 + g * 5) * 8 + hq;
            const uint4* zp1 = (const uint4*)z + (size_t)(r1 * BT1 + g * 5) * 8 + hq;
#pragma unroll
            for (int i = 0; i < 5; i++) {
                uint4 va = zp0[(size_t)i * 8];
                uint4 vb = zp1[(size_t)i * 8];
                float2 f0 = h2f2(va.x), f1 = h2f2(va.y), f2 = h2f2(va.z), f3 = h2f2(va.w);
                acc[i][0].x += nm0 * f0.x; acc[i][0].y += nm0 * f0.y;
                acc[i][1].x += nm0 * f1.x; acc[i][1].y += nm0 * f1.y;
                acc[i][2].x += nm0 * f2.x; acc[i][2].y += nm0 * f2.y;
                acc[i][3].x += nm0 * f3.x; acc[i][3].y += nm0 * f3.y;
                float2 g0 = h2f2(vb.x), g1 = h2f2(vb.y), g2 = h2f2(vb.z), g3 = h2f2(vb.w);
                acc[i][0].x += nm1 * g0.x; acc[i][0].y += nm1 * g0.y;
                acc[i][1].x += nm1 * g1.x; acc[i][1].y += nm1 * g1.y;
                acc[i][2].x += nm1 * g2.x; acc[i][2].y += nm1 * g2.y;
                acc[i][3].x += nm1 * g3.x; acc[i][3].y += nm1 * g3.y;
            }
        }
        if (e < m) {
            int r0 = sr[e];
            float nm0 = sn[e];
            const uint4* zp0 = (const uint4*)z + (size_t)(r0 * BT1 + g * 5) * 8 + hq;
#pragma unroll
            for (int i = 0; i < 5; i++) {
                uint4 va = zp0[(size_t)i * 8];
                float2 f0 = h2f2(va.x), f1 = h2f2(va.y), f2 = h2f2(va.z), f3 = h2f2(va.w);
                acc[i][0].x += nm0 * f0.x; acc[i][0].y += nm0 * f0.y;
                acc[i][1].x += nm0 * f1.x; acc[i][1].y += nm0 * f1.y;
                acc[i][2].x += nm0 * f2.x; acc[i][2].y += nm0 * f2.y;
                acc[i][3].x += nm0 * f3.x; acc[i][3].y += nm0 * f3.y;
            }
        }
        __syncthreads();
    }
    uint4* op = (uint4*)out + (size_t)(j * BT1 + g * 5) * 8 + hq;
    if (mode == 0) {
#pragma unroll
        for (int i = 0; i < 5; i++) {
            uint4 o4;
            o4.x = pack_h2(acc[i][0].x, acc[i][0].y);
            o4.y = pack_h2(acc[i][1].x, acc[i][1].y);
            o4.z = pack_h2(acc[i][2].x, acc[i][2].y);
            o4.w = pack_h2(acc[i][3].x, acc[i][3].y);
            op[(size_t)i * 8] = o4;
        }
    } else {
        const uint4* sp = (const uint4*)g_T0h + (size_t)(j * BT1 + g * 5) * 8 + hq;
#pragma unroll
        for (int i = 0; i < 5; i++) {
            uint4 s0 = sp[(size_t)i * 8];
            float2 t0 = h2f2(s0.x), t1 = h2f2(s0.y), t2 = h2f2(s0.z), t3 = h2f2(s0.w);
            uint4 o4;
            o4.x = pack_h2(2.f * acc[i][0].x - t0.x, 2.f * acc[i][0].y - t0.y);
            o4.y = pack_h2(2.f * acc[i][1].x - t1.x, 2.f * acc[i][1].y - t1.y);
            o4.z = pack_h2(2.f * acc[i][2].x - t2.x, 2.f * acc[i][2].y - t2.y);
            o4.w = pack_h2(2.f * acc[i][3].x - t3.x, 2.f * acc[i][3].y - t3.y);
            op[(size_t)i * 8] = o4;
        }
    }
}

// ---------------- cheb combine: fp16 mma m16n8k16 ----------------
__global__ __launch_bounds__(256) void k_chebmm(const float* __restrict__ chebB)
{
    __shared__ uint32_t sA[64 * A_ST];
    __shared__ uint32_t sB[16 * B_ST];
    int m0 = blockIdx.x * 64;
    int tid = threadIdx.x;
    int lane = tid & 31, w = tid >> 5;
    int mw = w & 3, nh = w >> 2;
    int r = lane >> 2, c = lane & 3;

    float acc[4][4];
#pragma unroll
    for (int nt = 0; nt < 4; nt++)
#pragma unroll
        for (int i = 0; i < 4; i++) acc[nt][i] = 0.f;

    const __half* srcs[3] = { g_T0h, g_Tx1h, g_Tx2h };
    for (int s = 0; s < 3; s++) {
        const uint4* gA = (const uint4*)(srcs[s] + (size_t)m0 * HIDc);
#pragma unroll
        for (int q = 0; q < 2; q++) {
            int i4 = tid + q * 256;
            int row = i4 >> 3, h8 = i4 & 7;
            *(uint4*)&sA[row * A_ST + h8 * 4] = gA[i4];
        }
        const uint2* gB = (const uint2*)g_cwh + s * 1024;
#pragma unroll
        for (int q = 0; q < 4; q++) {
            int i2 = tid + q * 256;
            int rr = i2 >> 6, nn = i2 & 63;
            *(uint2*)&sB[rr * B_ST + nn * 2] = gB[i2];
        }
        __syncthreads();
#pragma unroll
        for (int kc = 0; kc < 4; kc++) {
            uint32_t a[4];
            int abase = (mw * 16 + r) * A_ST + kc * 8 + c;
            a[0] = sA[abase];
            a[1] = sA[abase + 8 * A_ST];
            a[2] = sA[abase + 4];
            a[3] = sA[abase + 8 * A_ST + 4];
#pragma unroll
            for (int nt = 0; nt < 4; nt++) {
                uint2 bv = *(const uint2*)&sB[(kc * 4 + c) * B_ST + (nh * 32 + nt * 8 + r) * 2];
                mma_f16(acc[nt], a, bv.x, bv.y);
            }
        }
        __syncthreads();
    }
#pragma unroll
    for (int nt = 0; nt < 4; nt++) {
        int n0 = nh * 32 + nt * 8 + c * 2;
        float bb0 = chebB[n0], bb1 = chebB[n0 + 1];
        float v0 = acc[nt][0] + bb0; v0 = v0 > 0.f ? v0 : 0.f;
        float v1 = acc[nt][1] + bb1; v1 = v1 > 0.f ? v1 : 0.f;
        float v2 = acc[nt][2] + bb0; v2 = v2 > 0.f ? v2 : 0.f;
        float v3 = acc[nt][3] + bb1; v3 = v3 > 0.f ? v3 : 0.f;
        *(uint32_t*)&g_Tgh[(size_t)(m0 + mw * 16 + r) * HIDc + n0] = pack_h2(v0, v1);
        *(uint32_t*)&g_Tgh[(size_t)(m0 + mw * 16 + r + 8) * HIDc + n0] = pack_h2(v2, v3);
    }
}

// ---------------- temporal conv 2: fp16 mma, A resident, b-frag reuse x2 ----------------
__global__ __launch_bounds__(256) void k_conv2(
    const float* __restrict__ b1, const float* __restrict__ b2, const float* __restrict__ b3)
{
    __shared__ uint32_t sA[BT1 * A_ST];
    __shared__ uint32_t sB[2 * B_W16];
    int n = blockIdx.y;
    int o0 = blockIdx.x * 64;
    int tid = threadIdx.x;
    int lane = tid & 31, w = tid >> 5;
    int mp = w & 3, nh = w >> 2;
    int r = lane >> 2, c = lane & 3;

    const uint4* gT = (const uint4*)(g_Tgh + (size_t)n * (BT1 * HIDc));
#pragma unroll
    for (int q = 0; q < 5; q++) {
        int i4 = tid + q * 256;
        int bt = i4 >> 3, h8 = i4 & 7;
        *(uint4*)&sA[bt * A_ST + h8 * 4] = gT[i4];
    }
    const uint2* gW2 = (const uint2*)g_wth;
#pragma unroll
    for (int q = 0; q < 3; q++) {
        int i2 = tid + q * 256;
        int rr = i2 >> 6, nn = i2 & 63;
        *(uint2*)&sB[rr * B_ST + nn * 2] = gW2[rr * 384 + o0 + nn];
    }
    __syncthreads();

    float acc[3][2][4][4];
#pragma unroll
    for (int s = 0; s < 3; s++)
#pragma unroll
        for (int mt = 0; mt < 2; mt++)
#pragma unroll
            for (int nt = 0; nt < 4; nt++)
#pragma unroll
                for (int i = 0; i < 4; i++) acc[s][mt][nt][i] = 0.f;

    for (int kc = 0; kc < 12; kc++) {
        int cur = (kc & 1) ? B_W16 : 0;
        if (kc < 11) {
            int nxt = B_W16 - cur;
            int gbase = (kc + 1) * 12 * 384;
#pragma unroll
            for (int q = 0; q < 3; q++) {
                int i2 = tid + q * 256;
                int rr = i2 >> 6, nn = i2 & 63;
                *(uint2*)&sB[nxt + rr * B_ST + nn * 2] = gW2[gbase + rr * 384 + o0 + nn];
            }
        }
        int dt = kc >> 2;
        int hb2 = (kc & 3) * 8;
        uint32_t a[2][4];
#pragma unroll
        for (int mt = 0; mt < 2; mt++) {
            int base0 = (20 * (2 * mp + mt) + r + dt) * A_ST + hb2 + c;
            a[mt][0] = sA[base0];
            a[mt][1] = sA[base0 + 10 * A_ST];
            a[mt][2] = sA[base0 + 4];
            a[mt][3] = sA[base0 + 10 * A_ST + 4];
        }
#pragma unroll
        for (int s = 0; s < 3; s++)
#pragma unroll
            for (int nt = 0; nt < 4; nt++) {
                uint2 bv = *(const uint2*)&sB[cur + (s * 4 + c) * B_ST + ((nh * 4 + nt) * 8 + r) * 2];
                mma_f16(acc[s][0][nt], a[0], bv.x, bv.y);
                mma_f16(acc[s][1][nt], a[1], bv.x, bv.y);
            }
        __syncthreads();
    }

    int col2 = c * 2;
    float lsum = 0.f, lss = 0.f;
#pragma unroll
    for (int nt = 0; nt < 4; nt++) {
#pragma unroll
        for (int cc = 0; cc < 2; cc++) {
            int o = o0 + (nh * 4 + nt) * 8 + col2 + cc;
            float bias1 = b1[o], bias2 = b2[o], bias3 = b3[o];
#pragma unroll
            for (int mt = 0; mt < 2; mt++) {
#pragma unroll
                for (int rh = 0; rh < 2; rh++) {
                    float P = acc[0][mt][nt][rh * 2 + cc] + bias1;
                    float Q = acc[1][mt][nt][rh * 2 + cc] + bias2;
                    float R = acc[2][mt][nt][rh * 2 + cc] + bias3;
                    float sg = 1.f / (1.f + expf(-Q));
                    float v = P * sg + R;
                    v = v > 0.f ? v : 0.f;
                    lsum += v;
                    lss += v * v;
                    if (r == 7) {
                        int b = 2 * (2 * mp + mt) + rh;
                        g_last[(size_t)(b * Nn + n) * OC + o] = v;
                    }
                }
            }
        }
    }

#pragma unroll
    for (int off = 16; off > 0; off >>= 1) {
        lsum += __shfl_down_sync(0xffffffffu, lsum, off);
        lss  += __shfl_down_sync(0xffffffffu, lss,  off);
    }
    __shared__ float wsum[8], wss[8];
    if (lane == 0) { wsum[w] = lsum; wss[w] = lss; }
    __syncthreads();
    if (tid == 0) {
        float ts = 0.f, tq = 0.f;
#pragma unroll
        for (int i = 0; i < 8; i++) { ts += wsum[i]; tq += wss[i]; }
        atomicAdd(&g_sum[n], ts);
        atomicAdd(&g_sumsq[n], tq);
    }
}

// ---------------- final: BN + coalesced transpose via smem tile ----------------
__global__ __launch_bounds__(256) void k_final(
    const float* __restrict__ gamma, const float* __restrict__ beta,
    float* __restrict__ out)
{
    __shared__ float s[32][129];
    __shared__ float smean[32], sinv[32], sga[32], sbe[32];
    int n0 = blockIdx.x * 32;
    int c0 = blockIdx.y * 128;
    int b  = blockIdx.z;
    int tid = threadIdx.x;
    if (tid < 32) {
        int n = n0 + tid;
        float mean = g_sum[n] / STAT_CNT;
        float var = g_sumsq[n] / STAT_CNT - mean * mean;
        smean[tid] = mean;
        sinv[tid] = rsqrtf(var + 1e-5f);
        sga[tid] = gamma[n];
        sbe[tid] = beta[n];
    }
    int cl = tid & 63;
    int nl = tid >> 6;
#pragma unroll
    for (int i = 0; i < 8; i++) {
        int nn = nl + i * 4;
        float2 v = *(const float2*)&g_last[((size_t)(b * Nn) + n0 + nn) * OC + c0 + cl * 2];
        s[nn][cl * 2] = v.x;
        s[nn][cl * 2 + 1] = v.y;
    }
    __syncthreads();
    int nw = tid & 31, cw = tid >> 5;
    float mean = smean[nw], inv = sinv[nw];
    float ga = sga[nw], be = sbe[nw];
#pragma unroll
    for (int j = 0; j < 16; j++) {
        int c = cw + j * 8;
        out[(size_t)(c0 + c) * (Bsz * Nn) + b * Nn + n0 + nw] =
            (s[nw][c] - mean) * inv * ga + be;
    }
}

// ---------------- launch ----------------
extern "C" void kernel_launch(void* const* d_in, const int* in_sizes, int n_in,
                              void* d_out, int out_size)
{
    const float* X        = (const float*)d_in[0];
    const int*   ei       = (const int*)  d_in[1];
    const float* ew       = (const float*)d_in[2];
    const float* tc1_w1   = (const float*)d_in[3];
    const float* tc1_b1   = (const float*)d_in[4];
    const float* tc1_w2   = (const float*)d_in[5];
    const float* tc1_b2   = (const float*)d_in[6];
    const float* tc1_w3   = (const float*)d_in[7];
    const float* tc1_b3   = (const float*)d_in[8];
    const float* cheb_W   = (const float*)d_in[9];
    const float* cheb_b   = (const float*)d_in[10];
    const float* tc2_w1   = (const float*)d_in[11];
    const float* tc2_b1   = (const float*)d_in[12];
    const float* tc2_w2   = (const float*)d_in[13];
    const float* tc2_b2   = (const float*)d_in[14];
    const float* tc2_w3   = (const float*)d_in[15];
    const float* tc2_b3   = (const float*)d_in[16];
    const float* bn_gamma = (const float*)d_in[17];
    const float* bn_beta  = (const float*)d_in[18];
    float* out = (float*)d_out;

    k_csr<<<1, 1024>>>(ei, ew);
    k_conv1<<<Bsz * Nn, 64>>>(X, tc1_w1, tc1_b1, tc1_w2, tc1_b2, tc1_w3, tc1_b3);
    k_wprep<<<(110592 + 6144 + 255) / 256, 256>>>(tc2_w1, tc2_w2, tc2_w3, cheb_W);
    k_prop<<<Nn, 256>>>(0);
    k_prop<<<Nn, 256>>>(1);
    k_chebmm<<<(Nn * BT1) / 64, 256>>>(cheb_b);
    k_conv2<<<dim3(6, Nn), 256>>>(tc2_b1, tc2_b2, tc2_b3);
    k_final<<<dim3(32, 3, 16), 256>>>(bn_gamma, bn_beta, out);
}

// round 15
// speedup vs baseline: 1.9100x; 1.1414x over previous
#include <cuda_runtime.h>
#include <cuda_fp16.h>
#include <math.h>
#include <stdint.h>

// ---------------- problem constants ----------------
#define Bsz 16
#define Nn  1024
#define HIDc 64
#define T1  10
#define OC  384
#define Ee  16384
#define BT1 (Bsz*T1)    // 160
#define STAT_CNT 49152.0f

// smem strides (u32 units)
#define A_ST 36          // 64 halves = 32 u32 + 4 pad -> a-frag 4r+c conflict-free
#define B_ST 136         // 128 u32 payload + 8 pad -> b-frag LDS.64 conflict-free
#define B_W16 (12 * B_ST)

// ---------------- helpers ----------------
__device__ __forceinline__ uint32_t pack_h2(float x, float y) {
    __half2 h = __floats2half2_rn(x, y);
    return *reinterpret_cast<uint32_t*>(&h);
}
__device__ __forceinline__ float2 h2f2(uint32_t u) {
    __half2 h = *reinterpret_cast<__half2*>(&u);
    return __half22float2(h);
}
__device__ __forceinline__ void mma_f16(float c[4], const uint32_t a[4],
                                        uint32_t b0, uint32_t b1) {
    asm volatile(
        "mma.sync.aligned.m16n8k16.row.col.f32.f16.f16.f32 "
        "{%0,%1,%2,%3},{%4,%5,%6,%7},{%8,%9},{%0,%1,%2,%3};"
        : "+f"(c[0]), "+f"(c[1]), "+f"(c[2]), "+f"(c[3])
        : "r"(a[0]), "r"(a[1]), "r"(a[2]), "r"(a[3]), "r"(b0), "r"(b1));
}
__device__ __forceinline__ void cp_async8(uint32_t s_addr, const void* gptr) {
    asm volatile("cp.async.ca.shared.global [%0], [%1], 8;"
                 :: "r"(s_addr), "l"(gptr) : "memory");
}
__device__ __forceinline__ void cp_commit() {
    asm volatile("cp.async.commit_group;" ::: "memory");
}
__device__ __forceinline__ void cp_wait_all() {
    asm volatile("cp.async.wait_group 0;" ::: "memory");
}

// ---------------- device scratch ----------------
__device__ __half g_T0h [Nn*BT1*HIDc];
__device__ __half g_Tx1h[Nn*BT1*HIDc];
__device__ __half g_Tx2h[Nn*BT1*HIDc];
__device__ __half g_Tgh [Nn*BT1*HIDc];
__device__ float  g_last[Bsz*Nn*OC];
__device__ uint32_t g_wth[12*3*4*OC*2];  // [kc][s][c][o][p] half2-as-u32
__device__ uint32_t g_cwh[3*4*4*64*2];   // [s][kc][c][n][p]
__device__ int   g_cntv[Nn];
__device__ int   g_indptr[Nn];
__device__ int   g_csr_row[Ee];
__device__ float g_csr_nrm[Ee];
__device__ float g_sum[Nn];
__device__ float g_sumsq[Nn];

// ---------------- CSR build: one block, smem atomics ----------------
__global__ __launch_bounds__(1024) void k_csr(const int* __restrict__ ei,
                                              const float* __restrict__ ew) {
    __shared__ float sdeg[Nn];
    __shared__ int   scnt[Nn];
    __shared__ float sdinv[Nn];
    __shared__ int   sptr[Nn];
    __shared__ int   scounter[Nn];
    int t = threadIdx.x;
    sdeg[t] = 0.f; scnt[t] = 0; scounter[t] = 0;
    g_sum[t] = 0.f; g_sumsq[t] = 0.f;
    __syncthreads();
#pragma unroll
    for (int q = 0; q < 16; q++) {
        int e = t + q * 1024;
        int r = ei[e], c = ei[Ee + e];
        float w = ew[e];
        if (r != c) atomicAdd(&sdeg[r], w);
        atomicAdd(&scnt[c], 1);
    }
    __syncthreads();
    float d = sdeg[t];
    sdinv[t] = (d > 0.f) ? rsqrtf(d) : 0.f;
    int cval = scnt[t];
    sptr[t] = cval;
    __syncthreads();
    for (int off = 1; off < Nn; off <<= 1) {
        int v = (t >= off) ? sptr[t - off] : 0;
        __syncthreads();
        sptr[t] += v;
        __syncthreads();
    }
    int excl = sptr[t] - cval;
    __syncthreads();
    sptr[t] = excl;
    g_cntv[t] = cval;
    g_indptr[t] = excl;
    __syncthreads();
#pragma unroll
    for (int q = 0; q < 16; q++) {
        int e = t + q * 1024;
        int r = ei[e], c = ei[Ee + e];
        float w = ew[e];
        float nm = (r == c) ? 0.f : -(sdinv[r] * w * sdinv[c]);
        int pos = sptr[c] + atomicAdd(&scounter[c], 1);
        g_csr_row[pos] = r;
        g_csr_nrm[pos] = nm;
    }
}

// ---------------- temporal conv 1: 8 (n,b) units per block, smem weights ----------------
__global__ __launch_bounds__(512) void k_conv1(
    const float* __restrict__ X,
    const float* __restrict__ w1, const float* __restrict__ b1,
    const float* __restrict__ w2, const float* __restrict__ b2,
    const float* __restrict__ w3, const float* __restrict__ b3)
{
    __shared__ float sw1[384], sw2[384], sw3[384];
    __shared__ float sb1[64], sb2[64], sb3[64];
    __shared__ float sx[8][2][12];
    int tid = threadIdx.x;
    if (tid < 384) { sw1[tid] = w1[tid]; sw2[tid] = w2[tid]; sw3[tid] = w3[tid]; }
    else if (tid < 448) { int h = tid - 384; sb1[h] = b1[h]; sb2[h] = b2[h]; sb3[h] = b3[h]; }
    int unit = tid >> 6;                 // 0..7
    int h = tid & 63;
    int bid = blockIdx.x * 8 + unit;
    int n = bid >> 4, b = bid & 15;
    if (h < 24) {
        int c = h / 12, t = h % 12;
        sx[unit][c][t] = X[((b * Nn + n) * 2 + c) * 12 + t];
    }
    __syncthreads();
    float w1r[6], w2r[6], w3r[6];
#pragma unroll
    for (int j = 0; j < 6; j++) {
        w1r[j] = sw1[h * 6 + j];
        w2r[j] = sw2[h * 6 + j];
        w3r[j] = sw3[h * 6 + j];
    }
    float bb1 = sb1[h], bb2 = sb2[h], bb3 = sb3[h];
#pragma unroll
    for (int tp = 0; tp < T1; tp++) {
        float P = bb1, Q = bb2, R = bb3;
#pragma unroll
        for (int c = 0; c < 2; c++)
#pragma unroll
            for (int k = 0; k < 3; k++) {
                float v = sx[unit][c][tp + k];
                P += v * w1r[c * 3 + k];
                Q += v * w2r[c * 3 + k];
                R += v * w3r[c * 3 + k];
            }
        float sg = 1.f / (1.f + expf(-Q));
        float val = P * sg + R;
        val = val > 0.f ? val : 0.f;
        g_T0h[(n * BT1 + b * T1 + tp) * HIDc + h] = __float2half_rn(val);
    }
}

// ---------------- weight prep (merged): conv2 + cheb fp16 fragment layouts ----------------
__global__ void k_wprep(const float* __restrict__ w1,
                        const float* __restrict__ w2,
                        const float* __restrict__ w3,
                        const float* __restrict__ chebW)
{
    int idx = blockIdx.x * blockDim.x + threadIdx.x;
    if (idx < 110592) {
        int p = idx & 1;
        int rem = idx >> 1;
        int o = rem % 384;
        int rem2 = rem / 384;
        int c = rem2 & 3;
        int rem3 = rem2 >> 2;
        int s = rem3 % 3;
        int kc = rem3 / 3;
        const float* w = (s == 0) ? w1 : (s == 1) ? w2 : w3;
        int dt = kc >> 2;
        int h0 = (kc & 3) * 16 + 2 * c + 8 * p;
        float lo = w[(o * HIDc + h0) * 3 + dt];
        float hi = w[(o * HIDc + h0 + 1) * 3 + dt];
        g_wth[((kc * 3 + s) * 4 + c) * 768 + o * 2 + p] = pack_h2(lo, hi);
    } else if (idx < 110592 + 6144) {
        int j = idx - 110592;
        int p = j & 1;
        int n = (j >> 1) & 63;
        int c = (j >> 7) & 3;
        int kc = (j >> 9) & 3;
        int s = j >> 11;
        int k0 = kc * 16 + 2 * c + 8 * p;
        float lo = chebW[s * 4096 + k0 * HIDc + n];
        float hi = chebW[s * 4096 + (k0 + 1) * HIDc + n];
        g_cwh[j] = pack_h2(lo, hi);
    }
}

// ---------------- graph propagation: fp16 gather, fp32 accumulate, edge-unroll x2 ----------------
__global__ __launch_bounds__(256) void k_prop(int mode) {
    const __half* __restrict__ z = (mode == 0) ? g_T0h : g_Tx1h;
    __half* __restrict__ out = (mode == 0) ? g_Tx1h : g_Tx2h;
    int j = blockIdx.x;
    int tid = threadIdx.x;
    int hq = tid & 7;
    int g = tid >> 3;
    float2 acc[5][4];
#pragma unroll
    for (int i = 0; i < 5; i++)
#pragma unroll
        for (int k = 0; k < 4; k++) acc[i][k] = make_float2(0.f, 0.f);

    int start = g_indptr[j], cnt = g_cntv[j];
    __shared__ int sr[64];
    __shared__ float sn[64];
    for (int eb = 0; eb < cnt; eb += 64) {
        int m = cnt - eb; if (m > 64) m = 64;
        if (tid < m) { sr[tid] = g_csr_row[start + eb + tid]; sn[tid] = g_csr_nrm[start + eb + tid]; }
        __syncthreads();
        int e = 0;
        for (; e + 2 <= m; e += 2) {
            int r0 = sr[e], r1 = sr[e + 1];
            float nm0 = sn[e], nm1 = sn[e + 1];
            const uint4* zp0 = (const uint4*)z + (size_t)(r0 * BT1 + g * 5) * 8 + hq;
            const uint4* zp1 = (const uint4*)z + (size_t)(r1 * BT1 + g * 5) * 8 + hq;
#pragma unroll
            for (int i = 0; i < 5; i++) {
                uint4 va = zp0[(size_t)i * 8];
                uint4 vb = zp1[(size_t)i * 8];
                float2 f0 = h2f2(va.x), f1 = h2f2(va.y), f2 = h2f2(va.z), f3 = h2f2(va.w);
                acc[i][0].x += nm0 * f0.x; acc[i][0].y += nm0 * f0.y;
                acc[i][1].x += nm0 * f1.x; acc[i][1].y += nm0 * f1.y;
                acc[i][2].x += nm0 * f2.x; acc[i][2].y += nm0 * f2.y;
                acc[i][3].x += nm0 * f3.x; acc[i][3].y += nm0 * f3.y;
                float2 g0 = h2f2(vb.x), g1 = h2f2(vb.y), g2 = h2f2(vb.z), g3 = h2f2(vb.w);
                acc[i][0].x += nm1 * g0.x; acc[i][0].y += nm1 * g0.y;
                acc[i][1].x += nm1 * g1.x; acc[i][1].y += nm1 * g1.y;
                acc[i][2].x += nm1 * g2.x; acc[i][2].y += nm1 * g2.y;
                acc[i][3].x += nm1 * g3.x; acc[i][3].y += nm1 * g3.y;
            }
        }
        if (e < m) {
            int r0 = sr[e];
            float nm0 = sn[e];
            const uint4* zp0 = (const uint4*)z + (size_t)(r0 * BT1 + g * 5) * 8 + hq;
#pragma unroll
            for (int i = 0; i < 5; i++) {
                uint4 va = zp0[(size_t)i * 8];
                float2 f0 = h2f2(va.x), f1 = h2f2(va.y), f2 = h2f2(va.z), f3 = h2f2(va.w);
                acc[i][0].x += nm0 * f0.x; acc[i][0].y += nm0 * f0.y;
                acc[i][1].x += nm0 * f1.x; acc[i][1].y += nm0 * f1.y;
                acc[i][2].x += nm0 * f2.x; acc[i][2].y += nm0 * f2.y;
                acc[i][3].x += nm0 * f3.x; acc[i][3].y += nm0 * f3.y;
            }
        }
        __syncthreads();
    }
    uint4* op = (uint4*)out + (size_t)(j * BT1 + g * 5) * 8 + hq;
    if (mode == 0) {
#pragma unroll
        for (int i = 0; i < 5; i++) {
            uint4 o4;
            o4.x = pack_h2(acc[i][0].x, acc[i][0].y);
            o4.y = pack_h2(acc[i][1].x, acc[i][1].y);
            o4.z = pack_h2(acc[i][2].x, acc[i][2].y);
            o4.w = pack_h2(acc[i][3].x, acc[i][3].y);
            op[(size_t)i * 8] = o4;
        }
    } else {
        const uint4* sp = (const uint4*)g_T0h + (size_t)(j * BT1 + g * 5) * 8 + hq;
#pragma unroll
        for (int i = 0; i < 5; i++) {
            uint4 s0 = sp[(size_t)i * 8];
            float2 t0 = h2f2(s0.x), t1 = h2f2(s0.y), t2 = h2f2(s0.z), t3 = h2f2(s0.w);
            uint4 o4;
            o4.x = pack_h2(2.f * acc[i][0].x - t0.x, 2.f * acc[i][0].y - t0.y);
            o4.y = pack_h2(2.f * acc[i][1].x - t1.x, 2.f * acc[i][1].y - t1.y);
            o4.z = pack_h2(2.f * acc[i][2].x - t2.x, 2.f * acc[i][2].y - t2.y);
            o4.w = pack_h2(2.f * acc[i][3].x - t3.x, 2.f * acc[i][3].y - t3.y);
            op[(size_t)i * 8] = o4;
        }
    }
}

// ---------------- cheb combine: fp16 mma m16n8k16 ----------------
__global__ __launch_bounds__(256) void k_chebmm(const float* __restrict__ chebB)
{
    __shared__ uint32_t sA[64 * A_ST];
    __shared__ uint32_t sB[16 * B_ST];
    int m0 = blockIdx.x * 64;
    int tid = threadIdx.x;
    int lane = tid & 31, w = tid >> 5;
    int mw = w & 3, nh = w >> 2;
    int r = lane >> 2, c = lane & 3;

    float acc[4][4];
#pragma unroll
    for (int nt = 0; nt < 4; nt++)
#pragma unroll
        for (int i = 0; i < 4; i++) acc[nt][i] = 0.f;

    const __half* srcs[3] = { g_T0h, g_Tx1h, g_Tx2h };
    for (int s = 0; s < 3; s++) {
        const uint4* gA = (const uint4*)(srcs[s] + (size_t)m0 * HIDc);
#pragma unroll
        for (int q = 0; q < 2; q++) {
            int i4 = tid + q * 256;
            int row = i4 >> 3, h8 = i4 & 7;
            *(uint4*)&sA[row * A_ST + h8 * 4] = gA[i4];
        }
        const uint2* gB = (const uint2*)g_cwh + s * 1024;
#pragma unroll
        for (int q = 0; q < 4; q++) {
            int i2 = tid + q * 256;
            int rr = i2 >> 6, nn = i2 & 63;
            *(uint2*)&sB[rr * B_ST + nn * 2] = gB[i2];
        }
        __syncthreads();
#pragma unroll
        for (int kc = 0; kc < 4; kc++) {
            uint32_t a[4];
            int abase = (mw * 16 + r) * A_ST + kc * 8 + c;
            a[0] = sA[abase];
            a[1] = sA[abase + 8 * A_ST];
            a[2] = sA[abase + 4];
            a[3] = sA[abase + 8 * A_ST + 4];
#pragma unroll
            for (int nt = 0; nt < 4; nt++) {
                uint2 bv = *(const uint2*)&sB[(kc * 4 + c) * B_ST + (nh * 32 + nt * 8 + r) * 2];
                mma_f16(acc[nt], a, bv.x, bv.y);
            }
        }
        __syncthreads();
    }
#pragma unroll
    for (int nt = 0; nt < 4; nt++) {
        int n0 = nh * 32 + nt * 8 + c * 2;
        float bb0 = chebB[n0], bb1 = chebB[n0 + 1];
        float v0 = acc[nt][0] + bb0; v0 = v0 > 0.f ? v0 : 0.f;
        float v1 = acc[nt][1] + bb1; v1 = v1 > 0.f ? v1 : 0.f;
        float v2 = acc[nt][2] + bb0; v2 = v2 > 0.f ? v2 : 0.f;
        float v3 = acc[nt][3] + bb1; v3 = v3 > 0.f ? v3 : 0.f;
        *(uint32_t*)&g_Tgh[(size_t)(m0 + mw * 16 + r) * HIDc + n0] = pack_h2(v0, v1);
        *(uint32_t*)&g_Tgh[(size_t)(m0 + mw * 16 + r + 8) * HIDc + n0] = pack_h2(v2, v3);
    }
}

// ---------------- temporal conv 2: fp16 mma, A resident, cp.async B pipeline ----------------
__global__ __launch_bounds__(256) void k_conv2(
    const float* __restrict__ b1, const float* __restrict__ b2, const float* __restrict__ b3)
{
    __shared__ uint32_t sA[BT1 * A_ST];
    __shared__ uint32_t sB[2 * B_W16];
    int n = blockIdx.y;
    int o0 = blockIdx.x * 64;
    int tid = threadIdx.x;
    int lane = tid & 31, w = tid >> 5;
    int mp = w & 3, nh = w >> 2;
    int r = lane >> 2, c = lane & 3;

    // B loader indices (per thread: 3 8-byte copies per chunk)
    int l_rr[3], l_nn[3];
    uint32_t l_saddr[3];
#pragma unroll
    for (int q = 0; q < 3; q++) {
        int i2 = tid + q * 256;
        l_rr[q] = i2 >> 6; l_nn[q] = i2 & 63;
    }

    const uint4* gT = (const uint4*)(g_Tgh + (size_t)n * (BT1 * HIDc));
#pragma unroll
    for (int q = 0; q < 5; q++) {
        int i4 = tid + q * 256;
        int bt = i4 >> 3, h8 = i4 & 7;
        *(uint4*)&sA[bt * A_ST + h8 * 4] = gT[i4];
    }
    const uint2* gW2 = (const uint2*)g_wth;
    // prefetch B chunk 0 via cp.async
#pragma unroll
    for (int q = 0; q < 3; q++) {
        l_saddr[q] = (uint32_t)__cvta_generic_to_shared(&sB[l_rr[q] * B_ST + l_nn[q] * 2]);
        cp_async8(l_saddr[q], &gW2[l_rr[q] * 384 + o0 + l_nn[q]]);
    }
    cp_commit();
    cp_wait_all();
    __syncthreads();

    float acc[3][2][4][4];
#pragma unroll
    for (int s = 0; s < 3; s++)
#pragma unroll
        for (int mt = 0; mt < 2; mt++)
#pragma unroll
            for (int nt = 0; nt < 4; nt++)
#pragma unroll
                for (int i = 0; i < 4; i++) acc[s][mt][nt][i] = 0.f;

    for (int kc = 0; kc < 12; kc++) {
        int cur = (kc & 1) ? B_W16 : 0;
        if (kc < 11) {
            int nxt = B_W16 - cur;
            int gbase = (kc + 1) * 12 * 384;
#pragma unroll
            for (int q = 0; q < 3; q++) {
                uint32_t sa = l_saddr[q] + (uint32_t)(nxt - cur) * 4u
                              + (uint32_t)(cur ? 0 : 0);   // recompute below
                // compute addr directly (cheap): base buffer toggles each kc
                uint32_t dst = (uint32_t)__cvta_generic_to_shared(&sB[nxt + l_rr[q] * B_ST + l_nn[q] * 2]);
                cp_async8(dst, &gW2[gbase + l_rr[q] * 384 + o0 + l_nn[q]]);
            }
            cp_commit();
        }
        int dt = kc >> 2;
        int hb2 = (kc & 3) * 8;
        uint32_t a[2][4];
#pragma unroll
        for (int mt = 0; mt < 2; mt++) {
            int base0 = (20 * (2 * mp + mt) + r + dt) * A_ST + hb2 + c;
            a[mt][0] = sA[base0];
            a[mt][1] = sA[base0 + 10 * A_ST];
            a[mt][2] = sA[base0 + 4];
            a[mt][3] = sA[base0 + 10 * A_ST + 4];
        }
#pragma unroll
        for (int s = 0; s < 3; s++)
#pragma unroll
            for (int nt = 0; nt < 4; nt++) {
                uint2 bv = *(const uint2*)&sB[cur + (s * 4 + c) * B_ST + ((nh * 4 + nt) * 8 + r) * 2];
                mma_f16(acc[s][0][nt], a[0], bv.x, bv.y);
                mma_f16(acc[s][1][nt], a[1], bv.x, bv.y);
            }
        if (kc < 11) cp_wait_all();
        __syncthreads();
    }

    int col2 = c * 2;
    float lsum = 0.f, lss = 0.f;
#pragma unroll
    for (int nt = 0; nt < 4; nt++) {
#pragma unroll
        for (int cc = 0; cc < 2; cc++) {
            int o = o0 + (nh * 4 + nt) * 8 + col2 + cc;
            float bias1 = b1[o], bias2 = b2[o], bias3 = b3[o];
#pragma unroll
            for (int mt = 0; mt < 2; mt++) {
#pragma unroll
                for (int rh = 0; rh < 2; rh++) {
                    float P = acc[0][mt][nt][rh * 2 + cc] + bias1;
                    float Q = acc[1][mt][nt][rh * 2 + cc] + bias2;
                    float R = acc[2][mt][nt][rh * 2 + cc] + bias3;
                    float sg = 1.f / (1.f + expf(-Q));
                    float v = P * sg + R;
                    v = v > 0.f ? v : 0.f;
                    lsum += v;
                    lss += v * v;
                    if (r == 7) {
                        int b = 2 * (2 * mp + mt) + rh;
                        g_last[(size_t)(b * Nn + n) * OC + o] = v;
                    }
                }
            }
        }
    }

#pragma unroll
    for (int off = 16; off > 0; off >>= 1) {
        lsum += __shfl_down_sync(0xffffffffu, lsum, off);
        lss  += __shfl_down_sync(0xffffffffu, lss,  off);
    }
    __shared__ float wsum[8], wss[8];
    if (lane == 0) { wsum[w] = lsum; wss[w] = lss; }
    __syncthreads();
    if (tid == 0) {
        float ts = 0.f, tq = 0.f;
#pragma unroll
        for (int i = 0; i < 8; i++) { ts += wsum[i]; tq += wss[i]; }
        atomicAdd(&g_sum[n], ts);
        atomicAdd(&g_sumsq[n], tq);
    }
}

// ---------------- final: BN + coalesced transpose via smem tile ----------------
__global__ __launch_bounds__(256) void k_final(
    const float* __restrict__ gamma, const float* __restrict__ beta,
    float* __restrict__ out)
{
    __shared__ float s[32][129];
    __shared__ float smean[32], sinv[32], sga[32], sbe[32];
    int n0 = blockIdx.x * 32;
    int c0 = blockIdx.y * 128;
    int b  = blockIdx.z;
    int tid = threadIdx.x;
    if (tid < 32) {
        int n = n0 + tid;
        float mean = g_sum[n] / STAT_CNT;
        float var = g_sumsq[n] / STAT_CNT - mean * mean;
        smean[tid] = mean;
        sinv[tid] = rsqrtf(var + 1e-5f);
        sga[tid] = gamma[n];
        sbe[tid] = beta[n];
    }
    int cl = tid & 63;
    int nl = tid >> 6;
#pragma unroll
    for (int i = 0; i < 8; i++) {
        int nn = nl + i * 4;
        float2 v = *(const float2*)&g_last[((size_t)(b * Nn) + n0 + nn) * OC + c0 + cl * 2];
        s[nn][cl * 2] = v.x;
        s[nn][cl * 2 + 1] = v.y;
    }
    __syncthreads();
    int nw = tid & 31, cw = tid >> 5;
    float mean = smean[nw], inv = sinv[nw];
    float ga = sga[nw], be = sbe[nw];
#pragma unroll
    for (int j = 0; j < 16; j++) {
        int c = cw + j * 8;
        out[(size_t)(c0 + c) * (Bsz * Nn) + b * Nn + n0 + nw] =
            (s[nw][c] - mean) * inv * ga + be;
    }
}

// ---------------- launch ----------------
extern "C" void kernel_launch(void* const* d_in, const int* in_sizes, int n_in,
                              void* d_out, int out_size)
{
    const float* X        = (const float*)d_in[0];
    const int*   ei       = (const int*)  d_in[1];
    const float* ew       = (const float*)d_in[2];
    const float* tc1_w1   = (const float*)d_in[3];
    const float* tc1_b1   = (const float*)d_in[4];
    const float* tc1_w2   = (const float*)d_in[5];
    const float* tc1_b2   = (const float*)d_in[6];
    const float* tc1_w3   = (const float*)d_in[7];
    const float* tc1_b3   = (const float*)d_in[8];
    const float* cheb_W   = (const float*)d_in[9];
    const float* cheb_b   = (const float*)d_in[10];
    const float* tc2_w1   = (const float*)d_in[11];
    const float* tc2_b1   = (const float*)d_in[12];
    const float* tc2_w2   = (const float*)d_in[13];
    const float* tc2_b2   = (const float*)d_in[14];
    const float* tc2_w3   = (const float*)d_in[15];
    const float* tc2_b3   = (const float*)d_in[16];
    const float* bn_gamma = (const float*)d_in[17];
    const float* bn_beta  = (const float*)d_in[18];
    float* out = (float*)d_out;

    k_csr<<<1, 1024>>>(ei, ew);
    k_conv1<<<Bsz * Nn / 8, 512>>>(X, tc1_w1, tc1_b1, tc1_w2, tc1_b2, tc1_w3, tc1_b3);
    k_wprep<<<(110592 + 6144 + 255) / 256, 256>>>(tc2_w1, tc2_w2, tc2_w3, cheb_W);
    k_prop<<<Nn, 256>>>(0);
    k_prop<<<Nn, 256>>>(1);
    k_chebmm<<<(Nn * BT1) / 64, 256>>>(cheb_b);
    k_conv2<<<dim3(6, Nn), 256>>>(tc2_b1, tc2_b2, tc2_b3);
    k_final<<<dim3(32, 3, 16), 256>>>(bn_gamma, bn_beta, out);
}